// round 10
// baseline (speedup 1.0000x reference)
#include <cuda_runtime.h>
#include <cstdint>

#define BATCH 2
#define SEQ 2048
#define DIN 2048
#define DOUT 2048
#define TOPK 2

#define BM 128
#define BN 128
#define BK 32
#define NC (DIN / BK)          // 64 k-chunks
#define NSTAGE 4
#define NTHREADS 256

// stage = A(4096) + B(4096) floats = 32KB
#define A_STAGE_FLOATS 4096
#define STAGE_FLOATS 8192
#define SMEM_BIAS_F (NSTAGE * STAGE_FLOATS)            // 32768 floats
#define SMEM_FLOATS (SMEM_BIAS_F + BN)
#define SMEM_BYTES  (SMEM_FLOATS * 4)                  // 131584

// Fragment-packed scratch (__device__ globals: allocation-guard-safe).
// A: [b][kslab(256)][mtile(128)][lane(32)][4]   (float4 per lane)
// B: [b][kslab(256)][ntile(256)][lane(32)][2]   (float2 per lane)
__device__ __align__(16) float g_xa[(size_t)BATCH * SEQ * DIN];
__device__ __align__(16) float g_wb[(size_t)BATCH * DIN * DOUT];

__device__ __forceinline__ float to_tf32(float v) {
    uint32_t u;
    asm("cvt.rna.tf32.f32 %0, %1;" : "=r"(u) : "f"(v));
    return __uint_as_float(u);
}

__device__ __forceinline__ void mma_tf32(float c[4], const float a[4], const float b[2]) {
    const uint32_t* A = reinterpret_cast<const uint32_t*>(a);
    const uint32_t* B = reinterpret_cast<const uint32_t*>(b);
    asm volatile(
        "mma.sync.aligned.m16n8k8.row.col.f32.tf32.tf32.f32 "
        "{%0,%1,%2,%3}, {%4,%5,%6,%7}, {%8,%9}, {%0,%1,%2,%3};\n"
        : "+f"(c[0]), "+f"(c[1]), "+f"(c[2]), "+f"(c[3])
        : "r"(A[0]), "r"(A[1]), "r"(A[2]), "r"(A[3]), "r"(B[0]), "r"(B[1]));
}

// ---------------------------------------------------------------------------
// Fused pack kernel: blockIdx.x < 32 -> pack X tile; else -> pack W tile.
// ---------------------------------------------------------------------------
__global__ void pack_kernel(const float* __restrict__ x,
                            const int* __restrict__ sel_idx,
                            const float* __restrict__ sel_prob,
                            const float* __restrict__ weight) {
    __shared__ float tile[64][72];
    const int b = blockIdx.z;
    const int tid = threadIdx.x;
    const int warp = tid >> 5;
    const int lane = tid & 31;
    const int gp = lane >> 2, tg = lane & 3;

    if (blockIdx.x < 32) {
        // ---- X: 64 m-rows x 64 k-cols ----
        const int m0 = blockIdx.x * 64;
        const int k0 = blockIdx.y * 64;
        const float* xb = x + ((size_t)b * SEQ + m0) * DIN + k0;
#pragma unroll
        for (int i = 0; i < 4; ++i) {
            const int idx = tid + i * 256;
            const int r = idx >> 4;
            const int c4 = (idx & 15) << 2;
            const float4 v = *(const float4*)(xb + (size_t)r * DIN + c4);
            tile[r][c4 + 0] = to_tf32(v.x);
            tile[r][c4 + 1] = to_tf32(v.y);
            tile[r][c4 + 2] = to_tf32(v.z);
            tile[r][c4 + 3] = to_tf32(v.w);
        }
        __syncthreads();
        float4* o4 = (float4*)g_xa;
#pragma unroll
        for (int i = 0; i < 4; ++i) {
            const int pair = warp * 4 + i;          // 0..31
            const int mt = pair >> 3;               // mtile-local 0..3
            const int ks = pair & 7;                // kslab-local 0..7
            float4 r;
            r.x = tile[mt * 16 + gp][ks * 8 + tg];
            r.y = tile[mt * 16 + gp + 8][ks * 8 + tg];
            r.z = tile[mt * 16 + gp][ks * 8 + tg + 4];
            r.w = tile[mt * 16 + gp + 8][ks * 8 + tg + 4];
            const size_t f = ((size_t)b << 20) + ((size_t)(k0 / 8 + ks) << 12) +
                             ((size_t)(m0 / 16 + mt) << 5) + lane;
            o4[f] = r;
        }
    } else {
        // ---- W: superpose + pack, 64 k-rows x 64 n-cols ----
        const int k0 = (blockIdx.x - 32) * 64;
        const int n0 = blockIdx.y * 64;
        const int i0 = sel_idx[b * TOPK + 0];
        const int i1 = sel_idx[b * TOPK + 1];
        const float p0 = sel_prob[b * TOPK + 0];
        const float p1 = sel_prob[b * TOPK + 1];
        const float* w0 = weight + (size_t)i0 * DIN * DOUT + (size_t)k0 * DOUT + n0;
        const float* w1 = weight + (size_t)i1 * DIN * DOUT + (size_t)k0 * DOUT + n0;
#pragma unroll
        for (int i = 0; i < 4; ++i) {
            const int idx = tid + i * 256;
            const int r = idx >> 4;
            const int c4 = (idx & 15) << 2;
            const float4 va = *(const float4*)(w0 + (size_t)r * DOUT + c4);
            const float4 vb = *(const float4*)(w1 + (size_t)r * DOUT + c4);
            tile[r][c4 + 0] = to_tf32(p0 * va.x + p1 * vb.x);
            tile[r][c4 + 1] = to_tf32(p0 * va.y + p1 * vb.y);
            tile[r][c4 + 2] = to_tf32(p0 * va.z + p1 * vb.z);
            tile[r][c4 + 3] = to_tf32(p0 * va.w + p1 * vb.w);
        }
        __syncthreads();
        float2* o2 = (float2*)g_wb;
#pragma unroll
        for (int i = 0; i < 8; ++i) {
            const int pair = warp * 8 + i;          // 0..63
            const int ks = pair >> 3;               // kslab-local 0..7
            const int nt = pair & 7;                // ntile-local 0..7
            float2 r;
            r.x = tile[ks * 8 + tg][nt * 8 + gp];
            r.y = tile[ks * 8 + tg + 4][nt * 8 + gp];
            const size_t f = ((size_t)b << 21) + ((size_t)(k0 / 8 + ks) << 13) +
                             ((size_t)(n0 / 8 + nt) << 5) + lane;
            o2[f] = r;
        }
    }
}

// ---------------------------------------------------------------------------
// GEMM: BM=128 x BN=128, BK=32, 4-stage cp.async, 8 warps of 64x32.
// Register-double-buffered fragments: LDS of ks+1 issues under the HMMA
// stream of ks, breaking the per-ks phase-locked stall window.
// ---------------------------------------------------------------------------
__global__ void __launch_bounds__(NTHREADS, 1)
gemm_kernel(const int* __restrict__ sel_idx,
            const float* __restrict__ sel_prob,
            const float* __restrict__ bias,
            float* __restrict__ out) {
    extern __shared__ float smem[];
    const int tid = threadIdx.x;
    const int warp = tid >> 5;
    const int lane = tid & 31;
    const int gp = lane >> 2;
    const int tg = lane & 3;
    const int warp_m = warp >> 2;   // 0..1  (64-row slab)
    const int warp_n = warp & 3;    // 0..3  (32-col slab)
    const int bz = blockIdx.z;
    const int mt0 = blockIdx.y * (BM / 16);   // 8 mtiles per block
    const int nt0 = blockIdx.x * (BN / 8);    // 16 ntiles per block

    if (tid < BN) {
        const int i0 = sel_idx[bz * TOPK + 0];
        const int i1 = sel_idx[bz * TOPK + 1];
        const float p0 = sel_prob[bz * TOPK + 0];
        const float p1 = sel_prob[bz * TOPK + 1];
        const int n0 = blockIdx.x * BN;
        smem[SMEM_BIAS_F + tid] =
            p0 * bias[i0 * DOUT + n0 + tid] + p1 * bias[i1 * DOUT + n0 + tid];
    }

    float acc[4][4][4];
#pragma unroll
    for (int mi = 0; mi < 4; ++mi)
#pragma unroll
        for (int ni = 0; ni < 4; ++ni)
#pragma unroll
            for (int r = 0; r < 4; ++r) acc[mi][ni][r] = 0.0f;

    const uint32_t sbase = (uint32_t)__cvta_generic_to_shared(smem);
    const float4* gA = (const float4*)g_xa + ((size_t)bz << 20);
    const float4* gB = (const float4*)g_wb + ((size_t)bz << 20);

    auto fill = [&](int s, int c) {
        // A: 1024 float4, 4/thread
#pragma unroll
        for (int i = 0; i < 4; ++i) {
            const int j = tid + i * NTHREADS;        // 0..1023
            const int ks = j >> 8;                   // kslab-local 0..3
            const int rem = j & 255;
            const int gks = c * 4 + ks;
            const size_t fa = ((size_t)gks << 12) +
                              ((size_t)(mt0 + (rem >> 5)) << 5) + (rem & 31);
            const uint32_t da = sbase + (uint32_t)((s * STAGE_FLOATS + j * 4) * 4);
            asm volatile("cp.async.cg.shared.global [%0], [%1], 16;"
                         :: "r"(da), "l"(gA + fa));
        }
        // B: 1024 float4, 4/thread  (float4 view of the float2 layout)
#pragma unroll
        for (int i = 0; i < 4; ++i) {
            const int j = tid + i * NTHREADS;        // 0..1023
            const int ks = j >> 8;
            const int rem = j & 255;
            const int gks = c * 4 + ks;
            const size_t fb = ((size_t)gks << 12) +
                              ((size_t)(nt0 + (rem >> 4)) << 4) + (rem & 15);
            const uint32_t db = sbase +
                (uint32_t)((s * STAGE_FLOATS + A_STAGE_FLOATS + j * 4) * 4);
            asm volatile("cp.async.cg.shared.global [%0], [%1], 16;"
                         :: "r"(db), "l"(gB + fb));
        }
        asm volatile("cp.async.commit_group;");
    };

    // fragment loader: one float4 (A) / float2 (B) per tile index
    auto ldfrag = [&](float a[4][4], float b[4][2],
                      const float* As, const float* Bs, int ks) {
#pragma unroll
        for (int mi = 0; mi < 4; ++mi) {
            const float4 v = *(const float4*)(As + ks * 1024 +
                                              (warp_m * 4 + mi) * 128 + lane * 4);
            a[mi][0] = v.x; a[mi][1] = v.y; a[mi][2] = v.z; a[mi][3] = v.w;
        }
#pragma unroll
        for (int ni = 0; ni < 4; ++ni) {
            const float2 v = *(const float2*)(Bs + ks * 1024 +
                                              (warp_n * 4 + ni) * 64 + lane * 2);
            b[ni][0] = v.x; b[ni][1] = v.y;
        }
    };

    fill(0, 0);
    fill(1, 1);
    fill(2, 2);

    float afr[2][4][4], bfr[2][4][2];

    for (int c = 0; c < NC; ++c) {
        const int s = c & (NSTAGE - 1);
        const int pend = (NC - 1 - c) < 2 ? (NC - 1 - c) : 2;
        if (pend == 2)      asm volatile("cp.async.wait_group 2;" ::: "memory");
        else if (pend == 1) asm volatile("cp.async.wait_group 1;" ::: "memory");
        else                asm volatile("cp.async.wait_group 0;" ::: "memory");
        __syncthreads();

        const float* As = smem + s * STAGE_FLOATS;
        const float* Bs = As + A_STAGE_FLOATS;

        // prefetch ks=0 fragments BEFORE the LDGSTS burst so LDS lands first
        ldfrag(afr[0], bfr[0], As, Bs, 0);

        if (c + 3 < NC) fill((c + 3) & (NSTAGE - 1), c + 3);

#pragma unroll
        for (int ks = 0; ks < 4; ++ks) {
            const int cur = ks & 1;
            if (ks < 3) ldfrag(afr[cur ^ 1], bfr[cur ^ 1], As, Bs, ks + 1);
#pragma unroll
            for (int mi = 0; mi < 4; ++mi)
#pragma unroll
                for (int ni = 0; ni < 4; ++ni)
                    mma_tf32(acc[mi][ni], afr[cur][mi], bfr[cur][ni]);
        }
    }

    // epilogue: acc + bias, float2 stores
    const int m0 = blockIdx.y * BM;
    const int n0 = blockIdx.x * BN;
    float* outb = out + (size_t)bz * SEQ * DOUT + (size_t)m0 * DOUT + n0;
#pragma unroll
    for (int mi = 0; mi < 4; ++mi) {
        const int r0 = warp_m * 64 + mi * 16 + gp;
#pragma unroll
        for (int ni = 0; ni < 4; ++ni) {
            const int cc = warp_n * 32 + ni * 8 + tg * 2;
            const float b0 = smem[SMEM_BIAS_F + cc];
            const float b1 = smem[SMEM_BIAS_F + cc + 1];
            const float2 v0 = make_float2(acc[mi][ni][0] + b0, acc[mi][ni][1] + b1);
            const float2 v1 = make_float2(acc[mi][ni][2] + b0, acc[mi][ni][3] + b1);
            *(float2*)(outb + (size_t)r0 * DOUT + cc) = v0;
            *(float2*)(outb + (size_t)(r0 + 8) * DOUT + cc) = v1;
        }
    }
}

extern "C" void kernel_launch(void* const* d_in, const int* in_sizes, int n_in,
                              void* d_out, int out_size) {
    const float* tensor   = (const float*)d_in[0];  // (B,S,H,Dh) fp32
    const int*   sel_idx  = (const int*)d_in[1];    // (B,TOPK) int32
    const float* sel_prob = (const float*)d_in[2];  // (B,TOPK) fp32
    const float* weight   = (const float*)d_in[3];  // (16,DIN,DOUT) fp32
    const float* bias     = (const float*)d_in[4];  // (16,DOUT) fp32
    float* out = (float*)d_out;

    {
        dim3 g(64, 32, BATCH);   // x<32: pack X, x>=32: pack W
        pack_kernel<<<g, 256>>>(tensor, sel_idx, sel_prob, weight);
    }

    cudaFuncSetAttribute(gemm_kernel,
                         cudaFuncAttributeMaxDynamicSharedMemorySize, SMEM_BYTES);
    dim3 grid(DOUT / BN, SEQ / BM, BATCH);
    gemm_kernel<<<grid, NTHREADS, SMEM_BYTES>>>(sel_idx, sel_prob, bias, out);
}

// round 11
// speedup vs baseline: 1.8922x; 1.8922x over previous
#include <cuda_runtime.h>
#include <cuda_fp16.h>
#include <cstdint>

#define BATCH 2
#define SEQ 2048
#define DIN 2048
#define DOUT 2048
#define TOPK 2

#define BM 128
#define BN 256
#define BK 64                  // 4 x k16 steps per chunk
#define NC (DIN / BK)          // 32 k-chunks
#define NSTAGE 4
#define NTHREADS 512

// stage = A(128x64 fp16 = 16KB) + B(256x64 fp16 = 32KB) = 48KB
#define A_STAGE_BYTES 16384
#define STAGE_BYTES   49152
#define SMEM_BIAS_B   (NSTAGE * STAGE_BYTES)           // 196608
#define SMEM_BYTES    (SMEM_BIAS_B + BN * 4)           // 197632

// Fragment-packed fp16 scratch (__device__ globals, allocation-guard-safe).
// A: [b][ks16(128)][mtile(128)][lane(32)] uint4  (8 fp16 = m16n8k16 A frag)
// B: [b][ks16(128)][ntile(256)][lane(32)] uint2  (4 fp16 = B frag)
__device__ __align__(16) uint4 g_xa[(size_t)BATCH * 128 * 128 * 32];
__device__ __align__(16) uint2 g_wb[(size_t)BATCH * 128 * 256 * 32];

__device__ __forceinline__ uint32_t h2(float lo, float hi) {
    __half2 h = __floats2half2_rn(lo, hi);
    return *reinterpret_cast<uint32_t*>(&h);
}

__device__ __forceinline__ void mma_f16(float c[4], const uint32_t a[4], const uint32_t b[2]) {
    asm volatile(
        "mma.sync.aligned.m16n8k16.row.col.f32.f16.f16.f32 "
        "{%0,%1,%2,%3}, {%4,%5,%6,%7}, {%8,%9}, {%0,%1,%2,%3};\n"
        : "+f"(c[0]), "+f"(c[1]), "+f"(c[2]), "+f"(c[3])
        : "r"(a[0]), "r"(a[1]), "r"(a[2]), "r"(a[3]), "r"(b[0]), "r"(b[1]));
}

// ---------------------------------------------------------------------------
// Fused pack kernel. blockIdx.x<32: X -> A-fragments; else: W -> B-fragments.
// 64x64 f32 tile staged in smem, converted to fp16 fragment layout.
// A frag (m16 x k16): a0=(gp, 2tg:2tg+1) a1=(gp+8, ..) a2=(gp, +8) a3=(gp+8, +8)
// B frag (k16 x n8):  b0=(2tg:2tg+1, gp) b1=(2tg+8:2tg+9, gp)
// ---------------------------------------------------------------------------
__global__ void pack_kernel(const float* __restrict__ x,
                            const int* __restrict__ sel_idx,
                            const float* __restrict__ sel_prob,
                            const float* __restrict__ weight) {
    __shared__ float tile[64][68];
    const int b = blockIdx.z;
    const int tid = threadIdx.x;
    const int warp = tid >> 5;
    const int lane = tid & 31;
    const int gp = lane >> 2, tg = lane & 3;

    if (blockIdx.x < 32) {
        // ---- X: 64 m-rows x 64 k-cols ----
        const int m0 = blockIdx.x * 64;
        const int k0 = blockIdx.y * 64;
        const float* xb = x + ((size_t)b * SEQ + m0) * DIN + k0;
#pragma unroll
        for (int i = 0; i < 4; ++i) {
            const int idx = tid + i * 256;
            const int r = idx >> 4;
            const int c4 = (idx & 15) << 2;
            const float4 v = *(const float4*)(xb + (size_t)r * DIN + c4);
            tile[r][c4 + 0] = v.x;
            tile[r][c4 + 1] = v.y;
            tile[r][c4 + 2] = v.z;
            tile[r][c4 + 3] = v.w;
        }
        __syncthreads();
#pragma unroll
        for (int i = 0; i < 2; ++i) {
            const int p = warp * 2 + i;             // 0..15
            const int mt = p >> 2;                  // mtile-local 0..3
            const int ks = p & 3;                   // ks16-local 0..3
            const int r0 = mt * 16 + gp;
            const int c0 = ks * 16 + tg * 2;
            uint4 r;
            r.x = h2(tile[r0][c0],         tile[r0][c0 + 1]);
            r.y = h2(tile[r0 + 8][c0],     tile[r0 + 8][c0 + 1]);
            r.z = h2(tile[r0][c0 + 8],     tile[r0][c0 + 9]);
            r.w = h2(tile[r0 + 8][c0 + 8], tile[r0 + 8][c0 + 9]);
            const size_t f = (((size_t)b * 128 + (k0 / 16 + ks)) * 128 +
                              (m0 / 16 + mt)) * 32 + lane;
            g_xa[f] = r;
        }
    } else {
        // ---- W: superpose + pack, 64 k-rows x 64 n-cols ----
        const int k0 = (blockIdx.x - 32) * 64;
        const int n0 = blockIdx.y * 64;
        const int i0 = sel_idx[b * TOPK + 0];
        const int i1 = sel_idx[b * TOPK + 1];
        const float p0 = sel_prob[b * TOPK + 0];
        const float p1 = sel_prob[b * TOPK + 1];
        const float* w0 = weight + (size_t)i0 * DIN * DOUT + (size_t)k0 * DOUT + n0;
        const float* w1 = weight + (size_t)i1 * DIN * DOUT + (size_t)k0 * DOUT + n0;
#pragma unroll
        for (int i = 0; i < 4; ++i) {
            const int idx = tid + i * 256;
            const int r = idx >> 4;
            const int c4 = (idx & 15) << 2;
            const float4 va = *(const float4*)(w0 + (size_t)r * DOUT + c4);
            const float4 vb = *(const float4*)(w1 + (size_t)r * DOUT + c4);
            tile[r][c4 + 0] = p0 * va.x + p1 * vb.x;
            tile[r][c4 + 1] = p0 * va.y + p1 * vb.y;
            tile[r][c4 + 2] = p0 * va.z + p1 * vb.z;
            tile[r][c4 + 3] = p0 * va.w + p1 * vb.w;
        }
        __syncthreads();
#pragma unroll
        for (int i = 0; i < 4; ++i) {
            const int p = warp * 4 + i;             // 0..31
            const int ks = p >> 3;                  // ks16-local 0..3
            const int nt = p & 7;                   // ntile-local 0..7
            const int kr = ks * 16 + tg * 2;
            const int nc = nt * 8 + gp;
            uint2 r;
            r.x = h2(tile[kr][nc],     tile[kr + 1][nc]);
            r.y = h2(tile[kr + 8][nc], tile[kr + 9][nc]);
            const size_t f = (((size_t)b * 128 + (k0 / 16 + ks)) * 256 +
                              (n0 / 8 + nt)) * 32 + lane;
            g_wb[f] = r;
        }
    }
}

// ---------------------------------------------------------------------------
// GEMM: fp16 m16n8k16, BM=128 x BN=256, BK=64, 4-stage cp.async,
// 16 warps of 64x32. Single barrier per chunk, fill(c+3) before compute.
// ---------------------------------------------------------------------------
__global__ void __launch_bounds__(NTHREADS, 1)
gemm_kernel(const int* __restrict__ sel_idx,
            const float* __restrict__ sel_prob,
            const float* __restrict__ bias,
            float* __restrict__ out) {
    extern __shared__ char smem[];
    const int tid = threadIdx.x;
    const int warp = tid >> 5;
    const int lane = tid & 31;
    const int gp = lane >> 2;
    const int tg = lane & 3;
    const int warp_m = warp >> 3;   // 0..1  (64-row slab)
    const int warp_n = warp & 7;    // 0..7  (32-col slab)
    const int bz = blockIdx.z;
    const int mt0 = blockIdx.y * (BM / 16);   // 8 mtiles per block
    const int nt0 = blockIdx.x * (BN / 8);    // 32 ntiles per block

    float* biass = (float*)(smem + SMEM_BIAS_B);
    if (tid < BN) {
        const int i0 = sel_idx[bz * TOPK + 0];
        const int i1 = sel_idx[bz * TOPK + 1];
        const float p0 = sel_prob[bz * TOPK + 0];
        const float p1 = sel_prob[bz * TOPK + 1];
        const int n0 = blockIdx.x * BN;
        biass[tid] = p0 * bias[i0 * DOUT + n0 + tid] + p1 * bias[i1 * DOUT + n0 + tid];
    }

    float acc[4][4][4];
#pragma unroll
    for (int mi = 0; mi < 4; ++mi)
#pragma unroll
        for (int ni = 0; ni < 4; ++ni)
#pragma unroll
            for (int r = 0; r < 4; ++r) acc[mi][ni][r] = 0.0f;

    const uint32_t sbase = (uint32_t)__cvta_generic_to_shared(smem);
    const uint4* gA = g_xa + ((size_t)bz * 128 * 128 * 32);
    const uint4* gB = (const uint4*)(g_wb + ((size_t)bz * 128 * 256 * 32));

    auto fill = [&](int s, int c) {
        // A: 1024 uint4, 2/thread; 256-uint4 contiguous runs per ks16
#pragma unroll
        for (int i = 0; i < 2; ++i) {
            const int j = tid + i * NTHREADS;        // 0..1023
            const int ks = j >> 8;                   // ks16-local 0..3
            const int rem = j & 255;
            const size_t fa = ((size_t)(c * 4 + ks) << 12) +
                              ((size_t)(mt0 + (rem >> 5)) << 5) + (rem & 31);
            const uint32_t da = sbase + (uint32_t)(s * STAGE_BYTES + j * 16);
            asm volatile("cp.async.cg.shared.global [%0], [%1], 16;"
                         :: "r"(da), "l"(gA + fa));
        }
        // B: 2048 uint4, 4/thread; 512-uint4 contiguous runs per ks16
#pragma unroll
        for (int i = 0; i < 4; ++i) {
            const int j = tid + i * NTHREADS;        // 0..2047
            const int ks = j >> 9;
            const int rem = j & 511;
            const size_t fb = ((size_t)(c * 4 + ks) << 12) +
                              ((size_t)nt0 << 4) + rem;
            const uint32_t db = sbase +
                (uint32_t)(s * STAGE_BYTES + A_STAGE_BYTES + j * 16);
            asm volatile("cp.async.cg.shared.global [%0], [%1], 16;"
                         :: "r"(db), "l"(gB + fb));
        }
        asm volatile("cp.async.commit_group;");
    };

    fill(0, 0);
    fill(1, 1);
    fill(2, 2);

    for (int c = 0; c < NC; ++c) {
        const int s = c & (NSTAGE - 1);
        const int pend = (NC - 1 - c) < 2 ? (NC - 1 - c) : 2;
        if (pend == 2)      asm volatile("cp.async.wait_group 2;" ::: "memory");
        else if (pend == 1) asm volatile("cp.async.wait_group 1;" ::: "memory");
        else                asm volatile("cp.async.wait_group 0;" ::: "memory");
        __syncthreads();

        if (c + 3 < NC) fill((c + 3) & (NSTAGE - 1), c + 3);

        const uint4* As = (const uint4*)(smem + s * STAGE_BYTES);
        const uint2* Bs = (const uint2*)(smem + s * STAGE_BYTES + A_STAGE_BYTES);
#pragma unroll
        for (int ks = 0; ks < 4; ++ks) {
            uint32_t a[4][4], bb[4][2];
#pragma unroll
            for (int mi = 0; mi < 4; ++mi) {
                const uint4 v = As[ks * 256 + (warp_m * 4 + mi) * 32 + lane];
                a[mi][0] = v.x; a[mi][1] = v.y; a[mi][2] = v.z; a[mi][3] = v.w;
            }
#pragma unroll
            for (int ni = 0; ni < 4; ++ni) {
                const uint2 v = Bs[ks * 1024 + (warp_n * 4 + ni) * 32 + lane];
                bb[ni][0] = v.x; bb[ni][1] = v.y;
            }
#pragma unroll
            for (int mi = 0; mi < 4; ++mi)
#pragma unroll
                for (int ni = 0; ni < 4; ++ni)
                    mma_f16(acc[mi][ni], a[mi], bb[ni]);
        }
    }

    // epilogue: acc + bias, float2 stores (d-frag layout same as tf32 case)
    const int m0 = blockIdx.y * BM;
    const int n0 = blockIdx.x * BN;
    float* outb = out + (size_t)bz * SEQ * DOUT + (size_t)m0 * DOUT + n0;
#pragma unroll
    for (int mi = 0; mi < 4; ++mi) {
        const int r0 = warp_m * 64 + mi * 16 + gp;
#pragma unroll
        for (int ni = 0; ni < 4; ++ni) {
            const int cc = warp_n * 32 + ni * 8 + tg * 2;
            const float b0 = biass[cc];
            const float b1 = biass[cc + 1];
            const float2 v0 = make_float2(acc[mi][ni][0] + b0, acc[mi][ni][1] + b1);
            const float2 v1 = make_float2(acc[mi][ni][2] + b0, acc[mi][ni][3] + b1);
            *(float2*)(outb + (size_t)r0 * DOUT + cc) = v0;
            *(float2*)(outb + (size_t)(r0 + 8) * DOUT + cc) = v1;
        }
    }
}

extern "C" void kernel_launch(void* const* d_in, const int* in_sizes, int n_in,
                              void* d_out, int out_size) {
    const float* tensor   = (const float*)d_in[0];  // (B,S,H,Dh) fp32
    const int*   sel_idx  = (const int*)d_in[1];    // (B,TOPK) int32
    const float* sel_prob = (const float*)d_in[2];  // (B,TOPK) fp32
    const float* weight   = (const float*)d_in[3];  // (16,DIN,DOUT) fp32
    const float* bias     = (const float*)d_in[4];  // (16,DOUT) fp32
    float* out = (float*)d_out;

    {
        dim3 g(64, 32, BATCH);   // x<32: pack X, x>=32: pack W
        pack_kernel<<<g, 256>>>(tensor, sel_idx, sel_prob, weight);
    }

    cudaFuncSetAttribute(gemm_kernel,
                         cudaFuncAttributeMaxDynamicSharedMemorySize, SMEM_BYTES);
    dim3 grid(DOUT / BN, SEQ / BM, BATCH);
    gemm_kernel<<<grid, NTHREADS, SMEM_BYTES>>>(sel_idx, sel_prob, bias, out);
}

// round 12
// speedup vs baseline: 2.0458x; 1.0812x over previous
#include <cuda_runtime.h>
#include <cuda_fp16.h>
#include <cstdint>

#define BATCH 2
#define SEQ 2048
#define DIN 2048
#define DOUT 2048
#define TOPK 2

#define BM 128
#define BN 256
#define BK 64                  // 4 x k16 steps per chunk
#define NC (DIN / BK)          // 32 k-chunks
#define NSTAGE 4
#define NTHREADS 512

// stage = A(128x64 fp16 = 16KB) + B(256x64 fp16 = 32KB) = 48KB
#define A_STAGE_BYTES 16384
#define STAGE_BYTES   49152
#define SMEM_MBAR_B   (NSTAGE * STAGE_BYTES)           // 196608
#define SMEM_BYTES    (SMEM_MBAR_B + 64)               // full[4] + empty[4]

// Fragment-packed fp16 scratch (__device__ globals, allocation-guard-safe).
// A: [b][ks16(128)][mtile(128)][lane(32)] uint4  (8 fp16 = m16n8k16 A frag)
// B: [b][ks16(128)][ntile(256)][lane(32)] uint2  (4 fp16 = B frag)
__device__ __align__(16) uint4 g_xa[(size_t)BATCH * 128 * 128 * 32];
__device__ __align__(16) uint2 g_wb[(size_t)BATCH * 128 * 256 * 32];

__device__ __forceinline__ uint32_t h2(float lo, float hi) {
    __half2 h = __floats2half2_rn(lo, hi);
    return *reinterpret_cast<uint32_t*>(&h);
}

__device__ __forceinline__ void mma_f16(float c[4], const uint32_t a[4], const uint32_t b[2]) {
    asm volatile(
        "mma.sync.aligned.m16n8k16.row.col.f32.f16.f16.f32 "
        "{%0,%1,%2,%3}, {%4,%5,%6,%7}, {%8,%9}, {%0,%1,%2,%3};\n"
        : "+f"(c[0]), "+f"(c[1]), "+f"(c[2]), "+f"(c[3])
        : "r"(a[0]), "r"(a[1]), "r"(a[2]), "r"(a[3]), "r"(b[0]), "r"(b[1]));
}

__device__ __forceinline__ void mbar_wait(uint32_t mbar, uint32_t parity) {
    asm volatile(
        "{\n\t.reg .pred P;\n\t"
        "WL_%=:\n\t"
        "mbarrier.try_wait.parity.acquire.cta.shared::cta.b64 P, [%0], %1, 0x989680;\n\t"
        "@!P bra WL_%=;\n\t}"
        :: "r"(mbar), "r"(parity) : "memory");
}

// ---------------------------------------------------------------------------
// Fused pack kernel. blockIdx.x<32: X -> A-fragments; else: W -> B-fragments.
// ---------------------------------------------------------------------------
__global__ void pack_kernel(const float* __restrict__ x,
                            const int* __restrict__ sel_idx,
                            const float* __restrict__ sel_prob,
                            const float* __restrict__ weight) {
    __shared__ float tile[64][68];
    const int b = blockIdx.z;
    const int tid = threadIdx.x;
    const int warp = tid >> 5;
    const int lane = tid & 31;
    const int gp = lane >> 2, tg = lane & 3;

    if (blockIdx.x < 32) {
        // ---- X: 64 m-rows x 64 k-cols ----
        const int m0 = blockIdx.x * 64;
        const int k0 = blockIdx.y * 64;
        const float* xb = x + ((size_t)b * SEQ + m0) * DIN + k0;
#pragma unroll
        for (int i = 0; i < 4; ++i) {
            const int idx = tid + i * 256;
            const int r = idx >> 4;
            const int c4 = (idx & 15) << 2;
            const float4 v = *(const float4*)(xb + (size_t)r * DIN + c4);
            tile[r][c4 + 0] = v.x;
            tile[r][c4 + 1] = v.y;
            tile[r][c4 + 2] = v.z;
            tile[r][c4 + 3] = v.w;
        }
        __syncthreads();
#pragma unroll
        for (int i = 0; i < 2; ++i) {
            const int p = warp * 2 + i;             // 0..15
            const int mt = p >> 2;                  // mtile-local 0..3
            const int ks = p & 3;                   // ks16-local 0..3
            const int r0 = mt * 16 + gp;
            const int c0 = ks * 16 + tg * 2;
            uint4 r;
            r.x = h2(tile[r0][c0],         tile[r0][c0 + 1]);
            r.y = h2(tile[r0 + 8][c0],     tile[r0 + 8][c0 + 1]);
            r.z = h2(tile[r0][c0 + 8],     tile[r0][c0 + 9]);
            r.w = h2(tile[r0 + 8][c0 + 8], tile[r0 + 8][c0 + 9]);
            const size_t f = (((size_t)b * 128 + (k0 / 16 + ks)) * 128 +
                              (m0 / 16 + mt)) * 32 + lane;
            g_xa[f] = r;
        }
    } else {
        // ---- W: superpose + pack, 64 k-rows x 64 n-cols ----
        const int k0 = (blockIdx.x - 32) * 64;
        const int n0 = blockIdx.y * 64;
        const int i0 = sel_idx[b * TOPK + 0];
        const int i1 = sel_idx[b * TOPK + 1];
        const float p0 = sel_prob[b * TOPK + 0];
        const float p1 = sel_prob[b * TOPK + 1];
        const float* w0 = weight + (size_t)i0 * DIN * DOUT + (size_t)k0 * DOUT + n0;
        const float* w1 = weight + (size_t)i1 * DIN * DOUT + (size_t)k0 * DOUT + n0;
#pragma unroll
        for (int i = 0; i < 4; ++i) {
            const int idx = tid + i * 256;
            const int r = idx >> 4;
            const int c4 = (idx & 15) << 2;
            const float4 va = *(const float4*)(w0 + (size_t)r * DOUT + c4);
            const float4 vb = *(const float4*)(w1 + (size_t)r * DOUT + c4);
            tile[r][c4 + 0] = p0 * va.x + p1 * vb.x;
            tile[r][c4 + 1] = p0 * va.y + p1 * vb.y;
            tile[r][c4 + 2] = p0 * va.z + p1 * vb.z;
            tile[r][c4 + 3] = p0 * va.w + p1 * vb.w;
        }
        __syncthreads();
#pragma unroll
        for (int i = 0; i < 4; ++i) {
            const int p = warp * 4 + i;             // 0..31
            const int ks = p >> 3;                  // ks16-local 0..3
            const int nt = p & 7;                   // ntile-local 0..7
            const int kr = ks * 16 + tg * 2;
            const int nc = nt * 8 + gp;
            uint2 r;
            r.x = h2(tile[kr][nc],     tile[kr + 1][nc]);
            r.y = h2(tile[kr + 8][nc], tile[kr + 9][nc]);
            const size_t f = (((size_t)b * 128 + (k0 / 16 + ks)) * 256 +
                              (n0 / 8 + nt)) * 32 + lane;
            g_wb[f] = r;
        }
    }
}

// ---------------------------------------------------------------------------
// GEMM: fp16 m16n8k16, BM=128 x BN=256, BK=64, 16 warps of 64x32.
// Warp-decoupled pipeline: full[s] (count 512) via cp.async.mbarrier.arrive,
// empty[s] (count 16) via one arrive per warp. No __syncthreads in mainloop.
// ---------------------------------------------------------------------------
__global__ void __launch_bounds__(NTHREADS, 1)
gemm_kernel(const int* __restrict__ sel_idx,
            const float* __restrict__ sel_prob,
            const float* __restrict__ bias,
            float* __restrict__ out) {
    extern __shared__ char smem[];
    const uint32_t sbase = (uint32_t)__cvta_generic_to_shared(smem);
    const int tid = threadIdx.x;
    const int warp = tid >> 5;
    const int lane = tid & 31;
    const int gp = lane >> 2;
    const int tg = lane & 3;
    const int warp_m = warp >> 3;   // 0..1  (64-row slab)
    const int warp_n = warp & 7;    // 0..7  (32-col slab)
    const int bz = blockIdx.z;
    const int mt0 = blockIdx.y * (BM / 16);
    const int nt0 = blockIdx.x * (BN / 8);

    const uint32_t mfull = sbase + SMEM_MBAR_B;        // full[s] = mfull + 8s
    const uint32_t mempty = sbase + SMEM_MBAR_B + 32;  // empty[s] = mempty + 8s

    if (tid == 0) {
#pragma unroll
        for (int s = 0; s < NSTAGE; ++s) {
            asm volatile("mbarrier.init.shared.b64 [%0], %1;"
                         :: "r"(mfull + s * 8), "r"(NTHREADS) : "memory");
            asm volatile("mbarrier.init.shared.b64 [%0], %1;"
                         :: "r"(mempty + s * 8), "r"(NTHREADS / 32) : "memory");
        }
    }
    __syncthreads();

    float acc[4][4][4];
#pragma unroll
    for (int mi = 0; mi < 4; ++mi)
#pragma unroll
        for (int ni = 0; ni < 4; ++ni)
#pragma unroll
            for (int r = 0; r < 4; ++r) acc[mi][ni][r] = 0.0f;

    const uint4* gA = g_xa + ((size_t)bz * 128 * 128 * 32);
    const uint4* gB = (const uint4*)(g_wb + ((size_t)bz * 128 * 256 * 32));

    auto fill = [&](int s, int c) {
        // A: 1024 uint4, 2/thread
#pragma unroll
        for (int i = 0; i < 2; ++i) {
            const int j = tid + i * NTHREADS;
            const int ks = j >> 8;
            const int rem = j & 255;
            const size_t fa = ((size_t)(c * 4 + ks) << 12) +
                              ((size_t)(mt0 + (rem >> 5)) << 5) + (rem & 31);
            const uint32_t da = sbase + (uint32_t)(s * STAGE_BYTES + j * 16);
            asm volatile("cp.async.cg.shared.global [%0], [%1], 16;"
                         :: "r"(da), "l"(gA + fa));
        }
        // B: 2048 uint4, 4/thread
#pragma unroll
        for (int i = 0; i < 4; ++i) {
            const int j = tid + i * NTHREADS;
            const int ks = j >> 9;
            const int rem = j & 511;
            const size_t fb = ((size_t)(c * 4 + ks) << 12) +
                              ((size_t)nt0 << 4) + rem;
            const uint32_t db = sbase +
                (uint32_t)(s * STAGE_BYTES + A_STAGE_BYTES + j * 16);
            asm volatile("cp.async.cg.shared.global [%0], [%1], 16;"
                         :: "r"(db), "l"(gB + fb));
        }
        // async arrival on full[s] when this thread's copies land
        asm volatile("cp.async.mbarrier.arrive.noinc.shared.b64 [%0];"
                     :: "r"(mfull + s * 8) : "memory");
    };

    fill(0, 0);
    fill(1, 1);
    fill(2, 2);

    for (int c = 0; c < NC; ++c) {
        // produce chunk c+3 (wait its stage free, ring-cycle parity)
        if (c + 3 < NC) {
            const int cp = c + 3;
            const int sp = cp & 3;
            const int rp = cp >> 2;
            if (rp > 0) mbar_wait(mempty + sp * 8, (rp - 1) & 1);
            fill(sp, cp);
        }
        // consume chunk c
        const int s = c & 3;
        mbar_wait(mfull + s * 8, (c >> 2) & 1);

        const uint4* As = (const uint4*)(smem + s * STAGE_BYTES);
        const uint2* Bs = (const uint2*)(smem + s * STAGE_BYTES + A_STAGE_BYTES);
#pragma unroll
        for (int ks = 0; ks < 4; ++ks) {
            uint32_t a[4][4], bb[4][2];
#pragma unroll
            for (int mi = 0; mi < 4; ++mi) {
                const uint4 v = As[ks * 256 + (warp_m * 4 + mi) * 32 + lane];
                a[mi][0] = v.x; a[mi][1] = v.y; a[mi][2] = v.z; a[mi][3] = v.w;
            }
#pragma unroll
            for (int ni = 0; ni < 4; ++ni) {
                const uint2 v = Bs[ks * 1024 + (warp_n * 4 + ni) * 32 + lane];
                bb[ni][0] = v.x; bb[ni][1] = v.y;
            }
#pragma unroll
            for (int mi = 0; mi < 4; ++mi)
#pragma unroll
                for (int ni = 0; ni < 4; ++ni)
                    mma_f16(acc[mi][ni], a[mi], bb[ni]);
        }
        // this warp done with stage s (MMA issue implies frag LDS completed)
        if (lane == 0) {
            asm volatile("mbarrier.arrive.shared.b64 _, [%0];"
                         :: "r"(mempty + s * 8) : "memory");
        }
    }

    // epilogue: acc + bias (gmem, L2-hot), float2 stores; warps exit staggered
    const int i0 = sel_idx[bz * TOPK + 0];
    const int i1 = sel_idx[bz * TOPK + 1];
    const float p0 = sel_prob[bz * TOPK + 0];
    const float p1 = sel_prob[bz * TOPK + 1];
    const int m0 = blockIdx.y * BM;
    const int n0 = blockIdx.x * BN;
    const float* b0p = bias + i0 * DOUT + n0;
    const float* b1p = bias + i1 * DOUT + n0;
    float* outb = out + (size_t)bz * SEQ * DOUT + (size_t)m0 * DOUT + n0;
#pragma unroll
    for (int ni = 0; ni < 4; ++ni) {
        const int cc = warp_n * 32 + ni * 8 + tg * 2;
        const float bv0 = p0 * b0p[cc] + p1 * b1p[cc];
        const float bv1 = p0 * b0p[cc + 1] + p1 * b1p[cc + 1];
#pragma unroll
        for (int mi = 0; mi < 4; ++mi) {
            const int r0 = warp_m * 64 + mi * 16 + gp;
            const float2 v0 = make_float2(acc[mi][ni][0] + bv0, acc[mi][ni][1] + bv1);
            const float2 v1 = make_float2(acc[mi][ni][2] + bv0, acc[mi][ni][3] + bv1);
            *(float2*)(outb + (size_t)r0 * DOUT + cc) = v0;
            *(float2*)(outb + (size_t)(r0 + 8) * DOUT + cc) = v1;
        }
    }
}

extern "C" void kernel_launch(void* const* d_in, const int* in_sizes, int n_in,
                              void* d_out, int out_size) {
    const float* tensor   = (const float*)d_in[0];  // (B,S,H,Dh) fp32
    const int*   sel_idx  = (const int*)d_in[1];    // (B,TOPK) int32
    const float* sel_prob = (const float*)d_in[2];  // (B,TOPK) fp32
    const float* weight   = (const float*)d_in[3];  // (16,DIN,DOUT) fp32
    const float* bias     = (const float*)d_in[4];  // (16,DOUT) fp32
    float* out = (float*)d_out;

    {
        dim3 g(64, 32, BATCH);   // x<32: pack X, x>=32: pack W
        pack_kernel<<<g, 256>>>(tensor, sel_idx, sel_prob, weight);
    }

    cudaFuncSetAttribute(gemm_kernel,
                         cudaFuncAttributeMaxDynamicSharedMemorySize, SMEM_BYTES);
    dim3 grid(DOUT / BN, SEQ / BM, BATCH);
    gemm_kernel<<<grid, NTHREADS, SMEM_BYTES>>>(sel_idx, sel_prob, bias, out);
}

// round 13
// speedup vs baseline: 2.2431x; 1.0964x over previous
#include <cuda_runtime.h>
#include <cuda_fp16.h>
#include <cstdint>

#define BATCH 2
#define SEQ 2048
#define DIN 2048
#define DOUT 2048
#define TOPK 2

#define BM 128
#define BN 256
#define BK 64                  // 4 x k16 steps per chunk
#define NC (DIN / BK)          // 32 k-chunks
#define NSTAGE 4
#define NTHREADS 256

// stage = A(128x64 fp16 = 16KB) + B(256x64 fp16 = 32KB) = 48KB
#define A_STAGE_BYTES 16384
#define STAGE_BYTES   49152
#define SMEM_MBAR_B   (NSTAGE * STAGE_BYTES)           // 196608
#define SMEM_BYTES    (SMEM_MBAR_B + 64)

// Fragment-packed fp16 scratch (__device__ globals, allocation-guard-safe).
// A: [b][ks16(128)][mtile(128)][lane(32)] uint4   (m16k16 A frag)
// B: [b][ks16(128)][npair(128)][lane(32)] uint4   (k16 x n16 = two B frags)
__device__ __align__(16) uint4 g_xa[(size_t)BATCH * 128 * 128 * 32];
__device__ __align__(16) uint4 g_wb[(size_t)BATCH * 128 * 128 * 32];

__device__ __forceinline__ uint32_t h2(float lo, float hi) {
    __half2 h = __floats2half2_rn(lo, hi);
    return *reinterpret_cast<uint32_t*>(&h);
}

__device__ __forceinline__ void mma_f16(float c[4], const uint32_t a[4],
                                        uint32_t b0, uint32_t b1) {
    asm volatile(
        "mma.sync.aligned.m16n8k16.row.col.f32.f16.f16.f32 "
        "{%0,%1,%2,%3}, {%4,%5,%6,%7}, {%8,%9}, {%0,%1,%2,%3};\n"
        : "+f"(c[0]), "+f"(c[1]), "+f"(c[2]), "+f"(c[3])
        : "r"(a[0]), "r"(a[1]), "r"(a[2]), "r"(a[3]), "r"(b0), "r"(b1));
}

__device__ __forceinline__ void mbar_wait(uint32_t mbar, uint32_t parity) {
    asm volatile(
        "{\n\t.reg .pred P;\n\t"
        "WL_%=:\n\t"
        "mbarrier.try_wait.parity.acquire.cta.shared::cta.b64 P, [%0], %1, 0x989680;\n\t"
        "@!P bra WL_%=;\n\t}"
        :: "r"(mbar), "r"(parity) : "memory");
}

// ---------------------------------------------------------------------------
// Fused pack kernel. blockIdx.x<32: X -> A-fragments; else: W -> B-fragments.
// ---------------------------------------------------------------------------
__global__ void pack_kernel(const float* __restrict__ x,
                            const int* __restrict__ sel_idx,
                            const float* __restrict__ sel_prob,
                            const float* __restrict__ weight) {
    __shared__ float tile[64][68];
    const int b = blockIdx.z;
    const int tid = threadIdx.x;
    const int warp = tid >> 5;
    const int lane = tid & 31;
    const int gp = lane >> 2, tg = lane & 3;

    if (blockIdx.x < 32) {
        // ---- X: 64 m-rows x 64 k-cols ----
        const int m0 = blockIdx.x * 64;
        const int k0 = blockIdx.y * 64;
        const float* xb = x + ((size_t)b * SEQ + m0) * DIN + k0;
#pragma unroll
        for (int i = 0; i < 4; ++i) {
            const int idx = tid + i * 256;
            const int r = idx >> 4;
            const int c4 = (idx & 15) << 2;
            const float4 v = *(const float4*)(xb + (size_t)r * DIN + c4);
            tile[r][c4 + 0] = v.x;
            tile[r][c4 + 1] = v.y;
            tile[r][c4 + 2] = v.z;
            tile[r][c4 + 3] = v.w;
        }
        __syncthreads();
#pragma unroll
        for (int i = 0; i < 2; ++i) {
            const int p = warp * 2 + i;             // 0..15
            const int mt = p >> 2;                  // mtile-local 0..3
            const int ks = p & 3;                   // ks16-local 0..3
            const int r0 = mt * 16 + gp;
            const int c0 = ks * 16 + tg * 2;
            uint4 r;
            r.x = h2(tile[r0][c0],         tile[r0][c0 + 1]);
            r.y = h2(tile[r0 + 8][c0],     tile[r0 + 8][c0 + 1]);
            r.z = h2(tile[r0][c0 + 8],     tile[r0][c0 + 9]);
            r.w = h2(tile[r0 + 8][c0 + 8], tile[r0 + 8][c0 + 9]);
            const size_t f = (((size_t)b * 128 + (k0 / 16 + ks)) * 128 +
                              (m0 / 16 + mt)) * 32 + lane;
            g_xa[f] = r;
        }
    } else {
        // ---- W: superpose + pack, 64 k-rows x 64 n-cols ----
        const int k0 = (blockIdx.x - 32) * 64;
        const int n0 = blockIdx.y * 64;
        const int i0 = sel_idx[b * TOPK + 0];
        const int i1 = sel_idx[b * TOPK + 1];
        const float p0 = sel_prob[b * TOPK + 0];
        const float p1 = sel_prob[b * TOPK + 1];
        const float* w0 = weight + (size_t)i0 * DIN * DOUT + (size_t)k0 * DOUT + n0;
        const float* w1 = weight + (size_t)i1 * DIN * DOUT + (size_t)k0 * DOUT + n0;
#pragma unroll
        for (int i = 0; i < 4; ++i) {
            const int idx = tid + i * 256;
            const int r = idx >> 4;
            const int c4 = (idx & 15) << 2;
            const float4 va = *(const float4*)(w0 + (size_t)r * DOUT + c4);
            const float4 vb = *(const float4*)(w1 + (size_t)r * DOUT + c4);
            tile[r][c4 + 0] = p0 * va.x + p1 * vb.x;
            tile[r][c4 + 1] = p0 * va.y + p1 * vb.y;
            tile[r][c4 + 2] = p0 * va.z + p1 * vb.z;
            tile[r][c4 + 3] = p0 * va.w + p1 * vb.w;
        }
        __syncthreads();
        // npair fragment: uint4 = {B(k,n), B(k+8,n), B(k,n+8), B(k+8,n+8)}
#pragma unroll
        for (int i = 0; i < 2; ++i) {
            const int p = warp * 2 + i;             // 0..15
            const int ks = p >> 2;                  // ks16-local 0..3
            const int np = p & 3;                   // npair-local 0..3
            const int kr = ks * 16 + tg * 2;
            const int nc = np * 16 + gp;
            uint4 r;
            r.x = h2(tile[kr][nc],         tile[kr + 1][nc]);
            r.y = h2(tile[kr + 8][nc],     tile[kr + 9][nc]);
            r.z = h2(tile[kr][nc + 8],     tile[kr + 1][nc + 8]);
            r.w = h2(tile[kr + 8][nc + 8], tile[kr + 9][nc + 8]);
            const size_t f = (((size_t)b * 128 + (k0 / 16 + ks)) * 128 +
                              (n0 / 16 + np)) * 32 + lane;
            g_wb[f] = r;
        }
    }
}

// ---------------------------------------------------------------------------
// GEMM: fp16 m16n8k16, BM=128 x BN=256, BK=64, 8 warps of 64x64.
// Warp-decoupled mbarrier pipeline, 256 threads.
// Crossbar traffic: A x4-dup + B x2-dup = 128KB/chunk (was 192KB).
// ---------------------------------------------------------------------------
__global__ void __launch_bounds__(NTHREADS, 1)
gemm_kernel(const int* __restrict__ sel_idx,
            const float* __restrict__ sel_prob,
            const float* __restrict__ bias,
            float* __restrict__ out) {
    extern __shared__ char smem[];
    const uint32_t sbase = (uint32_t)__cvta_generic_to_shared(smem);
    const int tid = threadIdx.x;
    const int warp = tid >> 5;
    const int lane = tid & 31;
    const int gp = lane >> 2;
    const int tg = lane & 3;
    const int warp_m = warp >> 2;   // 0..1  (64-row slab)
    const int warp_n = warp & 3;    // 0..3  (64-col slab)
    const int bz = blockIdx.z;
    const int mt0 = blockIdx.y * (BM / 16);   // 8 mtiles
    const int np0 = blockIdx.x * (BN / 16);   // 16 npairs

    const uint32_t mfull = sbase + SMEM_MBAR_B;
    const uint32_t mempty = sbase + SMEM_MBAR_B + 32;

    if (tid == 0) {
#pragma unroll
        for (int s = 0; s < NSTAGE; ++s) {
            asm volatile("mbarrier.init.shared.b64 [%0], %1;"
                         :: "r"(mfull + s * 8), "r"(NTHREADS) : "memory");
            asm volatile("mbarrier.init.shared.b64 [%0], %1;"
                         :: "r"(mempty + s * 8), "r"(NTHREADS / 32) : "memory");
        }
    }
    __syncthreads();

    float acc[4][8][4];
#pragma unroll
    for (int mi = 0; mi < 4; ++mi)
#pragma unroll
        for (int ni = 0; ni < 8; ++ni)
#pragma unroll
            for (int r = 0; r < 4; ++r) acc[mi][ni][r] = 0.0f;

    const uint4* gA = g_xa + ((size_t)bz * 128 * 128 * 32);
    const uint4* gB = g_wb + ((size_t)bz * 128 * 128 * 32);

    auto fill = [&](int s, int c) {
        // A: 1024 uint4, 4/thread
#pragma unroll
        for (int i = 0; i < 4; ++i) {
            const int j = tid + i * NTHREADS;        // 0..1023
            const int ks = j >> 8;
            const int rem = j & 255;
            const size_t fa = ((size_t)(c * 4 + ks) << 12) +
                              ((size_t)(mt0 + (rem >> 5)) << 5) + (rem & 31);
            const uint32_t da = sbase + (uint32_t)(s * STAGE_BYTES + j * 16);
            asm volatile("cp.async.cg.shared.global [%0], [%1], 16;"
                         :: "r"(da), "l"(gA + fa));
        }
        // B: 2048 uint4, 8/thread (npair layout)
#pragma unroll
        for (int i = 0; i < 8; ++i) {
            const int j = tid + i * NTHREADS;        // 0..2047
            const int ks = j >> 9;
            const int rem = j & 511;
            const size_t fb = ((size_t)(c * 4 + ks) << 12) +
                              ((size_t)(np0 + (rem >> 5)) << 5) + (rem & 31);
            const uint32_t db = sbase +
                (uint32_t)(s * STAGE_BYTES + A_STAGE_BYTES + j * 16);
            asm volatile("cp.async.cg.shared.global [%0], [%1], 16;"
                         :: "r"(db), "l"(gB + fb));
        }
        asm volatile("cp.async.mbarrier.arrive.noinc.shared.b64 [%0];"
                     :: "r"(mfull + s * 8) : "memory");
    };

    fill(0, 0);
    fill(1, 1);
    fill(2, 2);

    for (int c = 0; c < NC; ++c) {
        if (c + 3 < NC) {
            const int cp = c + 3;
            const int sp = cp & 3;
            const int rp = cp >> 2;
            if (rp > 0) mbar_wait(mempty + sp * 8, (rp - 1) & 1);
            fill(sp, cp);
        }
        const int s = c & 3;
        mbar_wait(mfull + s * 8, (c >> 2) & 1);

        const uint4* As = (const uint4*)(smem + s * STAGE_BYTES);
        const uint4* Bs = (const uint4*)(smem + s * STAGE_BYTES + A_STAGE_BYTES);
#pragma unroll
        for (int ks = 0; ks < 4; ++ks) {
            uint32_t a[4][4];
            uint4 bv[4];
#pragma unroll
            for (int mi = 0; mi < 4; ++mi) {
                const uint4 v = As[ks * 256 + (warp_m * 4 + mi) * 32 + lane];
                a[mi][0] = v.x; a[mi][1] = v.y; a[mi][2] = v.z; a[mi][3] = v.w;
            }
#pragma unroll
            for (int np = 0; np < 4; ++np)
                bv[np] = Bs[ks * 512 + (warp_n * 4 + np) * 32 + lane];
#pragma unroll
            for (int mi = 0; mi < 4; ++mi)
#pragma unroll
                for (int np = 0; np < 4; ++np) {
                    mma_f16(acc[mi][np * 2 + 0], a[mi], bv[np].x, bv[np].y);
                    mma_f16(acc[mi][np * 2 + 1], a[mi], bv[np].z, bv[np].w);
                }
        }
        if (lane == 0) {
            asm volatile("mbarrier.arrive.shared.b64 _, [%0];"
                         :: "r"(mempty + s * 8) : "memory");
        }
    }

    // epilogue: acc + bias (gmem, L2-hot), float2 stores
    const int i0 = sel_idx[bz * TOPK + 0];
    const int i1 = sel_idx[bz * TOPK + 1];
    const float p0 = sel_prob[bz * TOPK + 0];
    const float p1 = sel_prob[bz * TOPK + 1];
    const int m0 = blockIdx.y * BM;
    const int n0 = blockIdx.x * BN;
    const float* b0p = bias + i0 * DOUT + n0;
    const float* b1p = bias + i1 * DOUT + n0;
    float* outb = out + (size_t)bz * SEQ * DOUT + (size_t)m0 * DOUT + n0;
#pragma unroll
    for (int ni = 0; ni < 8; ++ni) {
        const int cc = warp_n * 64 + ni * 8 + tg * 2;
        const float bv0 = p0 * b0p[cc] + p1 * b1p[cc];
        const float bv1 = p0 * b0p[cc + 1] + p1 * b1p[cc + 1];
#pragma unroll
        for (int mi = 0; mi < 4; ++mi) {
            const int r0 = warp_m * 64 + mi * 16 + gp;
            const float2 v0 = make_float2(acc[mi][ni][0] + bv0, acc[mi][ni][1] + bv1);
            const float2 v1 = make_float2(acc[mi][ni][2] + bv0, acc[mi][ni][3] + bv1);
            *(float2*)(outb + (size_t)r0 * DOUT + cc) = v0;
            *(float2*)(outb + (size_t)(r0 + 8) * DOUT + cc) = v1;
        }
    }
}

extern "C" void kernel_launch(void* const* d_in, const int* in_sizes, int n_in,
                              void* d_out, int out_size) {
    const float* tensor   = (const float*)d_in[0];  // (B,S,H,Dh) fp32
    const int*   sel_idx  = (const int*)d_in[1];    // (B,TOPK) int32
    const float* sel_prob = (const float*)d_in[2];  // (B,TOPK) fp32
    const float* weight   = (const float*)d_in[3];  // (16,DIN,DOUT) fp32
    const float* bias     = (const float*)d_in[4];  // (16,DOUT) fp32
    float* out = (float*)d_out;

    {
        dim3 g(64, 32, BATCH);   // x<32: pack X, x>=32: pack W
        pack_kernel<<<g, 256>>>(tensor, sel_idx, sel_prob, weight);
    }

    cudaFuncSetAttribute(gemm_kernel,
                         cudaFuncAttributeMaxDynamicSharedMemorySize, SMEM_BYTES);
    dim3 grid(DOUT / BN, SEQ / BM, BATCH);
    gemm_kernel<<<grid, NTHREADS, SMEM_BYTES>>>(sel_idx, sel_prob, bias, out);
}